// round 2
// baseline (speedup 1.0000x reference)
#include <cuda_runtime.h>
#include <math.h>

#define NN 100000
#define NE 1600000
#define NB 391            // ceil(NN/256)

// ---------------- scratch (device globals: allocation-free) ----------------
__device__ __align__(16) float g_xin[NN * 64];
__device__ float g_degf[NN];
__device__ float g_degb[NN];
__device__ int   g_cntf[NN];
__device__ int   g_cntb[NN];
__device__ int   g_rowf[NN];
__device__ int   g_rowb[NN];
__device__ int   g_curf[NN];
__device__ int   g_curb[NN];
__device__ int   g_partf[512];
__device__ int   g_partb[512];
__device__ __align__(16) int2 g_csrf[NE];   // (src, bits(wf)) sorted by tgt
__device__ __align__(16) int2 g_csrb[NE];   // (tgt, bits(wb)) sorted by src

// ---------------- init counters/degrees ----------------
__global__ void k_init() {
    int i = blockIdx.x * blockDim.x + threadIdx.x;
    int st = gridDim.x * blockDim.x;
    for (int j = i; j < NN; j += st) {
        g_degf[j] = 0.f; g_degb[j] = 0.f;
        g_cntf[j] = 0;   g_cntb[j] = 0;
    }
}

// ---------------- weighted degrees + edge counts ----------------
__global__ void k_count(const int* __restrict__ ei, const float* __restrict__ ew) {
    int e = blockIdx.x * blockDim.x + threadIdx.x;
    if (e >= NE) return;
    int s = ei[e], t = ei[NE + e];
    float w = (s == t) ? 0.f : ew[e];
    atomicAdd(&g_degf[t], w);
    atomicAdd(&g_degb[s], w);
    atomicAdd(&g_cntf[t], 1);
    atomicAdd(&g_cntb[s], 1);
}

// ---------------- CSR offsets: block sums -> scan partials -> offsets ----------------
__global__ void k_blocksum() {
    __shared__ int sf[256], sb[256];
    int i = blockIdx.x * 256 + threadIdx.x;
    sf[threadIdx.x] = (i < NN) ? g_cntf[i] : 0;
    sb[threadIdx.x] = (i < NN) ? g_cntb[i] : 0;
    __syncthreads();
    for (int off = 128; off; off >>= 1) {
        if (threadIdx.x < off) {
            sf[threadIdx.x] += sf[threadIdx.x + off];
            sb[threadIdx.x] += sb[threadIdx.x + off];
        }
        __syncthreads();
    }
    if (threadIdx.x == 0) { g_partf[blockIdx.x] = sf[0]; g_partb[blockIdx.x] = sb[0]; }
}

__global__ void k_scanpart() {
    __shared__ int sf[512], sb[512];
    int t = threadIdx.x;
    int vf = (t < NB) ? g_partf[t] : 0;
    int vb = (t < NB) ? g_partb[t] : 0;
    sf[t] = vf; sb[t] = vb;
    __syncthreads();
    for (int off = 1; off < 512; off <<= 1) {
        int af = (t >= off) ? sf[t - off] : 0;
        int ab = (t >= off) ? sb[t - off] : 0;
        __syncthreads();
        sf[t] += af; sb[t] += ab;
        __syncthreads();
    }
    if (t < NB) { g_partf[t] = sf[t] - vf; g_partb[t] = sb[t] - vb; }   // exclusive
}

__global__ void k_offsets() {
    __shared__ int sf[256], sb[256];
    int i = blockIdx.x * 256 + threadIdx.x;
    int t = threadIdx.x;
    int cf = (i < NN) ? g_cntf[i] : 0;
    int cb = (i < NN) ? g_cntb[i] : 0;
    sf[t] = cf; sb[t] = cb;
    __syncthreads();
    for (int off = 1; off < 256; off <<= 1) {
        int af = (t >= off) ? sf[t - off] : 0;
        int ab = (t >= off) ? sb[t - off] : 0;
        __syncthreads();
        sf[t] += af; sb[t] += ab;
        __syncthreads();
    }
    if (i < NN) {
        int of = g_partf[blockIdx.x] + sf[t] - cf;
        int ob = g_partb[blockIdx.x] + sb[t] - cb;
        g_rowf[i] = of; g_curf[i] = of;
        g_rowb[i] = ob; g_curb[i] = ob;
    }
}

// ---------------- CSR placement with normalized weights ----------------
__global__ void k_build(const int* __restrict__ ei, const float* __restrict__ ew) {
    int e = blockIdx.x * blockDim.x + threadIdx.x;
    if (e >= NE) return;
    int s = ei[e], t = ei[NE + e];
    float w = (s == t) ? 0.f : ew[e];
    float df = g_degf[t], db = g_degb[s];
    float wf = (df > 0.f) ? w / df : 0.f;
    float wb = (db > 0.f) ? w / db : 0.f;
    int pf = atomicAdd(&g_curf[t], 1);
    g_csrf[pf] = make_int2(s, __float_as_int(wf));
    int pb = atomicAdd(&g_curb[s], 1);
    g_csrb[pb] = make_int2(t, __float_as_int(wb));
}

// ---------------- x_in = concat(x, x_hat_1, h) @ W_in + b_in ----------------
#define XTP 164
#define XIN_SMEM (((64 + 32) * XTP + 64) * 4)

__global__ __launch_bounds__(256) void k_xin(const float* __restrict__ x,
                                             const float* __restrict__ xh,
                                             const float* __restrict__ hh,
                                             const float* __restrict__ Win,
                                             const float* __restrict__ bin) {
    extern __shared__ float sm[];
    float* Wt   = sm;                 // [64][XTP]
    float* rows = Wt + 64 * XTP;      // [32][XTP]
    float* bs   = rows + 32 * XTP;    // [64]

    for (int i = threadIdx.x; i < 64 * XTP; i += 256) Wt[i] = 0.f;
    __syncthreads();
    for (int i = threadIdx.x; i < 161 * 64; i += 256) {
        int k = i >> 6, c = i & 63;
        Wt[c * XTP + k] = Win[i];
    }
    if (threadIdx.x < 64) bs[threadIdx.x] = bin[threadIdx.x];

    const int col = threadIdx.x & 63;
    const int grp = threadIdx.x >> 6;
    const int base = blockIdx.x * 32;

    __syncthreads();
    for (int i = threadIdx.x; i < 32 * XTP; i += 256) {
        int s = i / XTP, k = i - s * XTP;
        int n = base + s;
        float v = 0.f;
        if (k < 161) {
            v = (k == 0) ? x[n]
              : (k < 97) ? xh[(size_t)n * 96 + (k - 1)]
                         : hh[(size_t)n * 64 + (k - 97)];
        }
        rows[i] = v;
    }
    __syncthreads();

    float acc[8];
#pragma unroll
    for (int s = 0; s < 8; s++) acc[s] = 0.f;

    const float4* wp = reinterpret_cast<const float4*>(Wt + col * XTP);
    const float4* rp = reinterpret_cast<const float4*>(rows + grp * 8 * XTP);
#pragma unroll
    for (int k4 = 0; k4 < XTP / 4; k4++) {
        float4 w = wp[k4];
#pragma unroll
        for (int s = 0; s < 8; s++) {
            float4 v = rp[s * (XTP / 4) + k4];
            acc[s] += w.x * v.x + w.y * v.y + w.z * v.z + w.w * v.w;
        }
    }
    float b = bs[col];
#pragma unroll
    for (int s = 0; s < 8; s++) {
        int n = base + grp * 8 + s;
        g_xin[(size_t)n * 64 + col] = acc[s] + b;
    }
}

// ---------------- per-warp CSR gather: dest[2*lane .. 2*lane+1] ----------------
__device__ __forceinline__ void gather_row(const int2* __restrict__ csr,
                                           int beg, int cnt, int lane,
                                           float* __restrict__ dest) {
    float a0 = 0.f, a1 = 0.f, c0 = 0.f, c1 = 0.f;
    for (int i = 0; i < cnt; i += 32) {
        int m = min(32, cnt - i);
        int2 ent = make_int2(0, 0);
        if (lane < m) ent = csr[beg + i + lane];
        int j = 0;
        for (; j + 1 < m; j += 2) {
            int   s0 = __shfl_sync(0xFFFFFFFFu, ent.x, j);
            float w0 = __int_as_float(__shfl_sync(0xFFFFFFFFu, ent.y, j));
            int   s1 = __shfl_sync(0xFFFFFFFFu, ent.x, j + 1);
            float w1 = __int_as_float(__shfl_sync(0xFFFFFFFFu, ent.y, j + 1));
            float2 v0 = *reinterpret_cast<const float2*>(g_xin + (size_t)s0 * 64 + 2 * lane);
            float2 v1 = *reinterpret_cast<const float2*>(g_xin + (size_t)s1 * 64 + 2 * lane);
            a0 += w0 * v0.x; a1 += w0 * v0.y;
            c0 += w1 * v1.x; c1 += w1 * v1.y;
        }
        if (j < m) {
            int   s0 = __shfl_sync(0xFFFFFFFFu, ent.x, j);
            float w0 = __int_as_float(__shfl_sync(0xFFFFFFFFu, ent.y, j));
            float2 v0 = *reinterpret_cast<const float2*>(g_xin + (size_t)s0 * 64 + 2 * lane);
            a0 += w0 * v0.x; a1 += w0 * v0.y;
        }
    }
    reinterpret_cast<float2*>(dest)[lane] = make_float2(a0 + c0, a1 + c1);
}

// ---------------- fused gather + filter GEMV + GMM heads + outputs ----------------
#define JP 132
#define HEAD_SMEM ((64 * JP + 3 * 32 * JP + 160 + 8 * 4 * 128) * 4)

__global__ __launch_bounds__(256) void k_head(const float* __restrict__ hh,
                                              const float* __restrict__ Wf,  const float* __restrict__ bf,
                                              const float* __restrict__ Wm,  const float* __restrict__ bm,
                                              const float* __restrict__ Wsg, const float* __restrict__ bsg,
                                              const float* __restrict__ Wp,  const float* __restrict__ bp,
                                              float* __restrict__ out, int write_extra) {
    extern __shared__ float sm[];
    float* Wft = sm;                    // [64][JP]
    float* Wmt = Wft + 64 * JP;         // [32][JP]
    float* Wst = Wmt + 32 * JP;
    float* Wpt = Wst + 32 * JP;
    float* bfs = Wpt + 32 * JP;         // 64
    float* bms = bfs + 64;              // 32
    float* bss = bms + 32;              // 32
    float* bps = bss + 32;              // 32
    float* cat = bps + 32;              // [8 warps][4 nodes][128]

    for (int i = threadIdx.x; i < 64 * JP; i += 256) Wft[i] = 0.f;
    for (int i = threadIdx.x; i < 32 * JP; i += 256) { Wmt[i] = 0.f; Wst[i] = 0.f; Wpt[i] = 0.f; }
    __syncthreads();
    for (int i = threadIdx.x; i < 128 * 64; i += 256) {
        int j = i >> 6, c = i & 63;
        Wft[c * JP + j] = Wf[i];
    }
    for (int i = threadIdx.x; i < 128 * 32; i += 256) {
        int j = i >> 5, c = i & 31;
        Wmt[c * JP + j] = Wm[i];
        Wst[c * JP + j] = Wsg[i];
        Wpt[c * JP + j] = Wp[i];
    }
    if (threadIdx.x < 64) bfs[threadIdx.x] = bf[threadIdx.x];
    if (threadIdx.x < 32) {
        bms[threadIdx.x] = bm[threadIdx.x];
        bss[threadIdx.x] = bsg[threadIdx.x];
        bps[threadIdx.x] = bp[threadIdx.x];
    }
    __syncthreads();

    const int lane = threadIdx.x & 31;
    const int wrp  = threadIdx.x >> 5;
    float* mycat = cat + wrp * 4 * 128;

    float* ogmm = out;
    float* oo1  = out + (size_t)NN * 96;
    float* oh   = out + (size_t)NN * 96 + (size_t)NN * 128;

    int base = blockIdx.x * 32 + wrp * 4;          // 3125 blocks * 32 = NN exactly
    if (base >= NN) return;

    // 1) gather out_f / out_b into cat = [outf(64) | outb(64)] per node
#pragma unroll
    for (int s = 0; s < 4; s++) {
        int n = base + s;
        float* c = mycat + s * 128;
        gather_row(g_csrf, g_rowf[n], g_cntf[n], lane, c);
        gather_row(g_csrb, g_rowb[n], g_cntb[n], lane, c + 64);
    }
    __syncwarp();

    // 2) out = cat @ W_filt : lane computes cols lane and lane+32
    float a0[4] = {0.f, 0.f, 0.f, 0.f};
    float a1[4] = {0.f, 0.f, 0.f, 0.f};
    {
        const float4* w0p = reinterpret_cast<const float4*>(Wft + lane * JP);
        const float4* w1p = reinterpret_cast<const float4*>(Wft + (lane + 32) * JP);
#pragma unroll 8
        for (int j4 = 0; j4 < 32; j4++) {
            float4 w0 = w0p[j4], w1 = w1p[j4];
#pragma unroll
            for (int s = 0; s < 4; s++) {
                float4 v = reinterpret_cast<const float4*>(mycat + s * 128)[j4];
                a0[s] += w0.x * v.x + w0.y * v.y + w0.z * v.z + w0.w * v.w;
                a1[s] += w1.x * v.x + w1.y * v.y + w1.z * v.z + w1.w * v.w;
            }
        }
    }
    __syncwarp();

    // 3) rebuild cat in place as out1 = [out(64) | h(64)]
    float h0[4], h1[4];
#pragma unroll
    for (int s = 0; s < 4; s++) {
        size_t n = (size_t)(base + s);
        a0[s] += bfs[lane];
        a1[s] += bfs[lane + 32];
        h0[s] = hh[n * 64 + lane];
        h1[s] = hh[n * 64 + 32 + lane];
        float* c = mycat + s * 128;
        c[lane]      = a0[s];
        c[lane + 32] = a1[s];
        c[lane + 64] = h0[s];
        c[lane + 96] = h1[s];
    }
    __syncwarp();

    // 4) heads: lane computes mu[lane], sigma[lane], pi[lane]
    float am[4] = {0.f, 0.f, 0.f, 0.f};
    float as_[4] = {0.f, 0.f, 0.f, 0.f};
    float ap[4] = {0.f, 0.f, 0.f, 0.f};
    {
        const float4* wmp = reinterpret_cast<const float4*>(Wmt + lane * JP);
        const float4* wsp = reinterpret_cast<const float4*>(Wst + lane * JP);
        const float4* wpp = reinterpret_cast<const float4*>(Wpt + lane * JP);
#pragma unroll 8
        for (int j4 = 0; j4 < 32; j4++) {
            float4 wm = wmp[j4], ws = wsp[j4], wq = wpp[j4];
#pragma unroll
            for (int s = 0; s < 4; s++) {
                float4 v = reinterpret_cast<const float4*>(mycat + s * 128)[j4];
                am[s]  += wm.x * v.x + wm.y * v.y + wm.z * v.z + wm.w * v.w;
                as_[s] += ws.x * v.x + ws.y * v.y + ws.z * v.z + ws.w * v.w;
                ap[s]  += wq.x * v.x + wq.y * v.y + wq.z * v.z + wq.w * v.w;
            }
        }
    }

    // 5) epilogue per node: softplus / softmax + all output writes
#pragma unroll
    for (int s = 0; s < 4; s++) {
        size_t n = (size_t)(base + s);
        float mu = am[s] + bms[lane];
        float sg = as_[s] + bss[lane];
        sg = fmaxf(sg, 0.f) + log1pf(__expf(-fabsf(sg)));   // stable softplus
        float pv = ap[s] + bps[lane];
        float m = pv;
#pragma unroll
        for (int o = 16; o; o >>= 1) m = fmaxf(m, __shfl_xor_sync(0xFFFFFFFFu, m, o));
        float ex = __expf(pv - m);
        float ssum = ex;
#pragma unroll
        for (int o = 16; o; o >>= 1) ssum += __shfl_xor_sync(0xFFFFFFFFu, ssum, o);
        float pi = ex / ssum;

        ogmm[n * 96 + lane]      = mu;
        ogmm[n * 96 + 32 + lane] = sg;
        ogmm[n * 96 + 64 + lane] = pi;
        if (write_extra) {
            oo1[n * 128 + lane]      = a0[s];
            oo1[n * 128 + 32 + lane] = a1[s];
            oo1[n * 128 + 64 + lane] = h0[s];
            oo1[n * 128 + 96 + lane] = h1[s];
            oh[n * 64 + lane]      = h0[s];
            oh[n * 64 + 32 + lane] = h1[s];
        }
    }
}

// ---------------- launch ----------------
extern "C" void kernel_launch(void* const* d_in, const int* in_sizes, int n_in,
                              void* d_out, int out_size) {
    const float* x   = (const float*)d_in[0];
    const float* xh  = (const float*)d_in[1];
    const float* h   = (const float*)d_in[2];
    const int*   ei  = (const int*)d_in[3];
    const float* ew  = (const float*)d_in[4];
    const float* Win = (const float*)d_in[5];
    const float* bin = (const float*)d_in[6];
    const float* Wf  = (const float*)d_in[7];
    const float* bf  = (const float*)d_in[8];
    const float* Wm  = (const float*)d_in[9];
    const float* bm  = (const float*)d_in[10];
    const float* Wsg = (const float*)d_in[11];
    const float* bsg = (const float*)d_in[12];
    const float* Wp  = (const float*)d_in[13];
    const float* bp  = (const float*)d_in[14];
    float* out = (float*)d_out;

    int write_extra = (out_size >= NN * 96 + NN * 128 + NN * 64) ? 1 : 0;

    cudaFuncSetAttribute(k_xin,  cudaFuncAttributeMaxDynamicSharedMemorySize, XIN_SMEM);
    cudaFuncSetAttribute(k_head, cudaFuncAttributeMaxDynamicSharedMemorySize, HEAD_SMEM);

    k_init<<<98, 256>>>();
    k_xin<<<3125, 256, XIN_SMEM>>>(x, xh, h, Win, bin);
    k_count<<<(NE + 255) / 256, 256>>>(ei, ew);
    k_blocksum<<<NB, 256>>>();
    k_scanpart<<<1, 512>>>();
    k_offsets<<<NB, 256>>>();
    k_build<<<(NE + 255) / 256, 256>>>(ei, ew);
    k_head<<<3125, 256, HEAD_SMEM>>>(h, Wf, bf, Wm, bm, Wsg, bsg, Wp, bp, out, write_extra);
}

// round 3
// speedup vs baseline: 1.1985x; 1.1985x over previous
#include <cuda_runtime.h>
#include <math.h>

#define NN 100000
#define NE 1600000
#define XTP 164

// ---------------- scratch (device globals: allocation-free) ----------------
__device__ __align__(16) float g_zf[NN * 64];    // x_in @ W_filt[:64,:]
__device__ __align__(16) float g_zb[NN * 64];    // x_in @ W_filt[64:,:]
__device__ __align__(16) float g_acc[NN * 64];   // diffused output accumulator
__device__ float g_degf[NN];
__device__ float g_degb[NN];
__device__ __align__(16) float g_Wc[128 * XTP];  // folded weights, transposed [c][k]
__device__ float g_bz[128];                      // folded bias

// ---------------- init accumulator + degrees ----------------
__global__ void k_init() {
    int i = blockIdx.x * blockDim.x + threadIdx.x;
    int st = gridDim.x * blockDim.x;
    float4 z = make_float4(0.f, 0.f, 0.f, 0.f);
    for (int j = i; j < NN * 16; j += st)
        reinterpret_cast<float4*>(g_acc)[j] = z;
    for (int j = i; j < NN; j += st) { g_degf[j] = 0.f; g_degb[j] = 0.f; }
}

// ---------------- fold W_filt into W_in:  Wc[c][k] = sum_j Win[k][j]*Wsel[j] ----------------
__global__ void k_wfold(const float* __restrict__ Win, const float* __restrict__ bin,
                        const float* __restrict__ Wf) {
    __shared__ float wsel[64];
    int c = blockIdx.x;                 // 0..127
    if (threadIdx.x < 64) {
        int j = threadIdx.x;
        wsel[j] = (c < 64) ? Wf[j * 64 + c] : Wf[(64 + j) * 64 + (c - 64)];
    }
    __syncthreads();
    int k = threadIdx.x;
    if (k < XTP) {
        float a = 0.f;
        if (k < 161) {
#pragma unroll 8
            for (int j = 0; j < 64; j++) a += Win[k * 64 + j] * wsel[j];
        }
        g_Wc[c * XTP + k] = a;
    }
    if (threadIdx.x == 0) {
        float b = 0.f;
        for (int j = 0; j < 64; j++) b += bin[j] * wsel[j];
        g_bz[c] = b;
    }
}

// ---------------- weighted degrees ----------------
__global__ void k_deg(const int* __restrict__ ei, const float* __restrict__ ew) {
    int e = blockIdx.x * blockDim.x + threadIdx.x;
    if (e >= NE) return;
    int s = ei[e], t = ei[NE + e];
    float w = ew[e];
    if (s != t) {
        atomicAdd(&g_degf[t], w);
        atomicAdd(&g_degb[s], w);
    }
}

// ---------------- z = concat(x, x_hat_1, h) @ Wc + bz ----------------
// 256 threads: col = tid&63 -> cols (col, col+64); grp = tid>>6 -> 8 rows. 32 rows/block.
#define Z_SMEM ((128 * XTP + 32 * XTP + 128) * 4)

__global__ __launch_bounds__(256) void k_z(const float* __restrict__ x,
                                           const float* __restrict__ xh,
                                           const float* __restrict__ hh) {
    extern __shared__ float sm[];
    float* Wt   = sm;                   // [128][XTP]
    float* rows = Wt + 128 * XTP;       // [32][XTP]
    float* bzs  = rows + 32 * XTP;      // [128]

    for (int i = threadIdx.x; i < 128 * XTP / 4; i += 256)
        reinterpret_cast<float4*>(Wt)[i] = reinterpret_cast<const float4*>(g_Wc)[i];
    if (threadIdx.x < 128) bzs[threadIdx.x] = g_bz[threadIdx.x];

    const int col = threadIdx.x & 63;
    const int grp = threadIdx.x >> 6;
    const int base = blockIdx.x * 32;

    for (int i = threadIdx.x; i < 32 * XTP; i += 256) {
        int s = i / XTP, k = i - s * XTP;
        int n = base + s;
        float v = 0.f;
        if (k < 161) {
            v = (k == 0) ? x[n]
              : (k < 97) ? xh[(size_t)n * 96 + (k - 1)]
                         : hh[(size_t)n * 64 + (k - 97)];
        }
        rows[i] = v;
    }
    __syncthreads();

    float a0[8], a1[8];
#pragma unroll
    for (int s = 0; s < 8; s++) { a0[s] = 0.f; a1[s] = 0.f; }

    const float4* w0p = reinterpret_cast<const float4*>(Wt + col * XTP);
    const float4* w1p = reinterpret_cast<const float4*>(Wt + (col + 64) * XTP);
    const float4* rp  = reinterpret_cast<const float4*>(rows + grp * 8 * XTP);
#pragma unroll
    for (int k4 = 0; k4 < XTP / 4; k4++) {
        float4 w0 = w0p[k4], w1 = w1p[k4];
#pragma unroll
        for (int s = 0; s < 8; s++) {
            float4 v = rp[s * (XTP / 4) + k4];
            a0[s] += w0.x * v.x + w0.y * v.y + w0.z * v.z + w0.w * v.w;
            a1[s] += w1.x * v.x + w1.y * v.y + w1.z * v.z + w1.w * v.w;
        }
    }
    float b0 = bzs[col], b1 = bzs[col + 64];
#pragma unroll
    for (int s = 0; s < 8; s++) {
        size_t n = (size_t)(base + grp * 8 + s);
        g_zf[n * 64 + col] = a0[s] + b0;
        g_zb[n * 64 + col] = a1[s] + b1;
    }
}

// ---------------- scatter: acc[t] += wf*zf[s]; acc[s] += wb*zb[t] ----------------
__device__ __forceinline__ void red4(float* p, float a, float b, float c, float d) {
    asm volatile("red.global.add.v4.f32 [%0], {%1, %2, %3, %4};"
                 :: "l"(p), "f"(a), "f"(b), "f"(c), "f"(d) : "memory");
}

__global__ __launch_bounds__(256) void k_scatter(const int* __restrict__ ei,
                                                 const float* __restrict__ ew) {
    unsigned tid = blockIdx.x * 256u + threadIdx.x;
    unsigned e = tid >> 4;               // 16 lanes per edge
    if (e >= NE) return;
    int sub = threadIdx.x & 15;

    int s = __ldg(&ei[e]);
    int t = __ldg(&ei[NE + e]);
    float w = __ldg(&ew[e]);
    if (s == t) w = 0.f;
    float df = __ldg(&g_degf[t]);
    float db = __ldg(&g_degb[s]);
    float wf = (df > 0.f) ? w / df : 0.f;
    float wb = (db > 0.f) ? w / db : 0.f;

    float4 vs = *reinterpret_cast<const float4*>(g_zf + (size_t)s * 64 + 4 * sub);
    red4(g_acc + (size_t)t * 64 + 4 * sub, wf * vs.x, wf * vs.y, wf * vs.z, wf * vs.w);
    float4 vt = *reinterpret_cast<const float4*>(g_zb + (size_t)t * 64 + 4 * sub);
    red4(g_acc + (size_t)s * 64 + 4 * sub, wb * vt.x, wb * vt.y, wb * vt.z, wb * vt.w);
}

// ---------------- fused GMM heads + outputs ----------------
#define JP 132
#define HEAD_SMEM ((3 * 32 * JP + 160 + 8 * 4 * 128) * 4)

__global__ __launch_bounds__(256) void k_head(const float* __restrict__ hh,
                                              const float* __restrict__ bf,
                                              const float* __restrict__ Wm,  const float* __restrict__ bm,
                                              const float* __restrict__ Wsg, const float* __restrict__ bsg,
                                              const float* __restrict__ Wp,  const float* __restrict__ bp,
                                              float* __restrict__ out, int write_extra) {
    extern __shared__ float sm[];
    float* Wmt = sm;                    // [32][JP]
    float* Wst = Wmt + 32 * JP;
    float* Wpt = Wst + 32 * JP;
    float* bfs = Wpt + 32 * JP;         // 64
    float* bms = bfs + 64;              // 32
    float* bss = bms + 32;              // 32
    float* bps = bss + 32;              // 32
    float* cat = bps + 32;              // [8 warps][4 nodes][128]

    for (int i = threadIdx.x; i < 32 * JP; i += 256) { Wmt[i] = 0.f; Wst[i] = 0.f; Wpt[i] = 0.f; }
    __syncthreads();
    for (int i = threadIdx.x; i < 128 * 32; i += 256) {
        int j = i >> 5, c = i & 31;
        Wmt[c * JP + j] = Wm[i];
        Wst[c * JP + j] = Wsg[i];
        Wpt[c * JP + j] = Wp[i];
    }
    if (threadIdx.x < 64) bfs[threadIdx.x] = bf[threadIdx.x];
    if (threadIdx.x < 32) {
        bms[threadIdx.x] = bm[threadIdx.x];
        bss[threadIdx.x] = bsg[threadIdx.x];
        bps[threadIdx.x] = bp[threadIdx.x];
    }
    __syncthreads();

    const int lane = threadIdx.x & 31;
    const int wrp  = threadIdx.x >> 5;
    float* mycat = cat + wrp * 4 * 128;

    float* ogmm = out;
    float* oo1  = out + (size_t)NN * 96;
    float* oh   = out + (size_t)NN * 96 + (size_t)NN * 128;

    int base = blockIdx.x * 32 + wrp * 4;          // 3125 * 32 = NN exactly

    // out1 = [acc + b_filt | h]
    float a0[4], a1[4], h0[4], h1[4];
#pragma unroll
    for (int s = 0; s < 4; s++) {
        size_t n = (size_t)(base + s);
        a0[s] = g_acc[n * 64 + lane]      + bfs[lane];
        a1[s] = g_acc[n * 64 + 32 + lane] + bfs[lane + 32];
        h0[s] = hh[n * 64 + lane];
        h1[s] = hh[n * 64 + 32 + lane];
        float* c = mycat + s * 128;
        c[lane]      = a0[s];
        c[lane + 32] = a1[s];
        c[lane + 64] = h0[s];
        c[lane + 96] = h1[s];
    }
    __syncwarp();

    // heads: lane computes mu[lane], sigma[lane], pi[lane] for 4 nodes
    float am[4] = {0.f, 0.f, 0.f, 0.f};
    float as_[4] = {0.f, 0.f, 0.f, 0.f};
    float ap[4] = {0.f, 0.f, 0.f, 0.f};
    {
        const float4* wmp = reinterpret_cast<const float4*>(Wmt + lane * JP);
        const float4* wsp = reinterpret_cast<const float4*>(Wst + lane * JP);
        const float4* wpp = reinterpret_cast<const float4*>(Wpt + lane * JP);
#pragma unroll 8
        for (int j4 = 0; j4 < 32; j4++) {
            float4 wm = wmp[j4], ws = wsp[j4], wq = wpp[j4];
#pragma unroll
            for (int s = 0; s < 4; s++) {
                float4 v = reinterpret_cast<const float4*>(mycat + s * 128)[j4];
                am[s]  += wm.x * v.x + wm.y * v.y + wm.z * v.z + wm.w * v.w;
                as_[s] += ws.x * v.x + ws.y * v.y + ws.z * v.z + ws.w * v.w;
                ap[s]  += wq.x * v.x + wq.y * v.y + wq.z * v.z + wq.w * v.w;
            }
        }
    }

    // epilogue: softplus / softmax + writes
#pragma unroll
    for (int s = 0; s < 4; s++) {
        size_t n = (size_t)(base + s);
        float mu = am[s] + bms[lane];
        float sg = as_[s] + bss[lane];
        sg = fmaxf(sg, 0.f) + log1pf(__expf(-fabsf(sg)));   // stable softplus
        float pv = ap[s] + bps[lane];
        float m = pv;
#pragma unroll
        for (int o = 16; o; o >>= 1) m = fmaxf(m, __shfl_xor_sync(0xFFFFFFFFu, m, o));
        float ex = __expf(pv - m);
        float ssum = ex;
#pragma unroll
        for (int o = 16; o; o >>= 1) ssum += __shfl_xor_sync(0xFFFFFFFFu, ssum, o);
        float pi = ex / ssum;

        ogmm[n * 96 + lane]      = mu;
        ogmm[n * 96 + 32 + lane] = sg;
        ogmm[n * 96 + 64 + lane] = pi;
        if (write_extra) {
            oo1[n * 128 + lane]      = a0[s];
            oo1[n * 128 + 32 + lane] = a1[s];
            oo1[n * 128 + 64 + lane] = h0[s];
            oo1[n * 128 + 96 + lane] = h1[s];
            oh[n * 64 + lane]      = h0[s];
            oh[n * 64 + 32 + lane] = h1[s];
        }
    }
}

// ---------------- launch ----------------
extern "C" void kernel_launch(void* const* d_in, const int* in_sizes, int n_in,
                              void* d_out, int out_size) {
    const float* x   = (const float*)d_in[0];
    const float* xh  = (const float*)d_in[1];
    const float* h   = (const float*)d_in[2];
    const int*   ei  = (const int*)d_in[3];
    const float* ew  = (const float*)d_in[4];
    const float* Win = (const float*)d_in[5];
    const float* bin = (const float*)d_in[6];
    const float* Wf  = (const float*)d_in[7];
    const float* bf  = (const float*)d_in[8];
    const float* Wm  = (const float*)d_in[9];
    const float* bm  = (const float*)d_in[10];
    const float* Wsg = (const float*)d_in[11];
    const float* bsg = (const float*)d_in[12];
    const float* Wp  = (const float*)d_in[13];
    const float* bp  = (const float*)d_in[14];
    float* out = (float*)d_out;

    int write_extra = (out_size >= NN * 96 + NN * 128 + NN * 64) ? 1 : 0;

    cudaFuncSetAttribute(k_z,    cudaFuncAttributeMaxDynamicSharedMemorySize, Z_SMEM);
    cudaFuncSetAttribute(k_head, cudaFuncAttributeMaxDynamicSharedMemorySize, HEAD_SMEM);

    k_init<<<148, 256>>>();
    k_wfold<<<128, 192>>>(Win, bin, Wf);
    k_deg<<<(NE + 255) / 256, 256>>>(ei, ew);
    k_z<<<3125, 256, Z_SMEM>>>(x, xh, h);
    k_scatter<<<(NE * 16 + 255) / 256, 256>>>(ei, ew);
    k_head<<<3125, 256, HEAD_SMEM>>>(h, bf, Wm, bm, Wsg, bsg, Wp, bp, out, write_extra);
}